// round 6
// baseline (speedup 1.0000x reference)
#include <cuda_runtime.h>
#include <math.h>

#define B_  16
#define T_  32
#define S_  128
#define F_  3
#define H_  256
#define NH_ 8
#define DK_ 32
#define TP_ 4
#define R_  2048      // rows per model GEMM (B*S)
#define NB  256       // persistent blocks (must all be co-resident: 256 <= 148*2)

// ---------------- device scratch (no allocations allowed) ----------------
__device__ float g_eh[2][R_*H_];
__device__ float g_ec[R_*H_];
__device__ float g_dh[2][R_*H_];
__device__ float g_qkv[2*R_*768];       // enc rows [0,2048), dec rows [2048,4096)
__device__ float g_ctx_e[R_*H_];
__device__ float g_ctx_d[R_*H_];
__device__ float g_code[R_*H_];
__device__ float g_We[H_*768];
__device__ float g_Wd[H_*768];
__device__ float g_Wge[(F_+2*H_)*4*H_];
__device__ float g_Wgd[(3*H_)*4*H_];
__device__ float g_bge[4*H_];
__device__ float g_bgd[4*H_];

__device__ unsigned g_bar_count;
__device__ unsigned g_bar_epoch;

__device__ __forceinline__ float sigmoidf_(float x) { return 1.0f / (1.0f + __expf(-x)); }

__device__ __forceinline__ float warp_sum(float v) {
    v += __shfl_xor_sync(0xffffffffu, v, 16);
    v += __shfl_xor_sync(0xffffffffu, v, 8);
    v += __shfl_xor_sync(0xffffffffu, v, 4);
    v += __shfl_xor_sync(0xffffffffu, v, 2);
    v += __shfl_xor_sync(0xffffffffu, v, 1);
    return v;
}

// ---------------- grid barrier (sense-reversing, replay-safe) ----------------
__device__ __forceinline__ void gsync() {
    __syncthreads();
    if (threadIdx.x == 0) {
        unsigned e;
        asm volatile("ld.acquire.gpu.u32 %0, [%1];" : "=r"(e) : "l"(&g_bar_epoch) : "memory");
        __threadfence();
        unsigned old = atomicAdd(&g_bar_count, 1u);
        if (old == NB - 1) {
            atomicExch(&g_bar_count, 0u);
            __threadfence();
            atomicAdd(&g_bar_epoch, 1u);
        } else {
            unsigned cur;
            do {
                __nanosleep(32);
                asm volatile("ld.acquire.gpu.u32 %0, [%1];" : "=r"(cur) : "l"(&g_bar_epoch) : "memory");
            } while (cur == e);
        }
    }
    __syncthreads();
}

// ---------------- segmented A loader ----------------
// AMODE 0: plain A0, ld=K
// AMODE 1: enc gates [x(3)|eh|ctx_e], K=515
// AMODE 2: dec gates [code|dh|ctx_d], K=768
// AMODE 3: qkv both: rows<2048 -> A1 (eh), else A2 (dh); K=256
template<int AMODE>
__device__ __forceinline__ float loadA(const float* __restrict__ A0,
                                       const float* __restrict__ A1,
                                       const float* __restrict__ A2,
                                       int gm, int gk, int K, int t) {
    if (AMODE == 0) {
        return (gk < K) ? A0[(size_t)gm * K + gk] : 0.0f;
    } else if (AMODE == 1) {
        if (gk >= F_ + 2 * H_) return 0.0f;
        if (gk < F_) {
            int b = gm >> 7, s = gm & (S_ - 1);
            return A0[(((size_t)b * T_ + t) * S_ + s) * F_ + gk];
        }
        if (gk < F_ + H_) return A1[(size_t)gm * H_ + (gk - F_)];
        return A2[(size_t)gm * H_ + (gk - F_ - H_)];
    } else if (AMODE == 2) {
        if (gk < H_)     return A0[(size_t)gm * H_ + gk];
        if (gk < 2 * H_) return A1[(size_t)gm * H_ + (gk - H_)];
        return A2[(size_t)gm * H_ + (gk - 2 * H_)];
    } else {
        const float* p = (gm < R_) ? A1 : A2;
        return p[(size_t)(gm & (R_ - 1)) * H_ + gk];
    }
}

__device__ __forceinline__ void mma_tf32(float* d, const unsigned* a, const unsigned* b) {
    asm volatile(
        "mma.sync.aligned.m16n8k8.row.col.f32.tf32.tf32.f32 "
        "{%0,%1,%2,%3}, {%4,%5,%6,%7}, {%8,%9}, {%0,%1,%2,%3};\n"
        : "+f"(d[0]), "+f"(d[1]), "+f"(d[2]), "+f"(d[3])
        : "r"(a[0]), "r"(a[1]), "r"(a[2]), "r"(a[3]), "r"(b[0]), "r"(b[1]));
}

// ---------------- tile-looped TF32 GEMM phase ----------------
// BM=128 BN=64 BK=16, 8 warps (4x2), warp tile 32x32 via m16n8k8 (2x4).
// EPI 0: raw  EPI 1: sigmoid(+bias)  EPI 2: fused LSTM (permuted gates)
template<int AMODE, int EPI>
__device__ __forceinline__ void gemm_phase(
    float As[2][128][20], float Bs[2][16][72],
    const float* __restrict__ A0, const float* __restrict__ A1,
    const float* __restrict__ A2, const float* __restrict__ Bm,
    const float* __restrict__ Bm2,   // alt B for AMODE 3 (dec rows)
    const float* __restrict__ bias, float* __restrict__ C,
    const float* __restrict__ c_in, float* __restrict__ c_out,
    int Mtiles, int Ntiles, int N, int K, int t)
{
    const int tid = threadIdx.x, lane = tid & 31, warp = tid >> 5;
    const int wm = warp >> 1, wn = warp & 1;
    const int q = lane & 3, rsel = lane >> 2;
    const int tot = Mtiles * Ntiles;

    for (int tile = blockIdx.x; tile < tot; tile += NB) {
        const int bm = (tile % Mtiles) * 128;
        const int bn = (tile / Mtiles) * 64;
        const float* Bt = (AMODE == 3 && bm >= R_) ? Bm2 : Bm;

        float acc[2][4][4];
#pragma unroll
        for (int i = 0; i < 2; i++)
#pragma unroll
            for (int j = 0; j < 4; j++)
#pragma unroll
                for (int l = 0; l < 4; l++) acc[i][j][l] = 0.0f;

        const int ntiles = (K + 15) >> 4;
        float ra[8], rb[4];

#pragma unroll
        for (int i = 0; i < 8; i++) {
            int idx = tid + i * 256; int m = idx >> 4, k = idx & 15;
            ra[i] = loadA<AMODE>(A0, A1, A2, bm + m, k, K, t);
        }
#pragma unroll
        for (int i = 0; i < 4; i++) {
            int idx = tid + i * 256; int k = idx >> 6, n = idx & 63;
            rb[i] = (k < K) ? Bt[(size_t)k * N + bn + n] : 0.0f;
        }
#pragma unroll
        for (int i = 0; i < 8; i++) { int idx = tid + i * 256; As[0][idx >> 4][idx & 15] = ra[i]; }
#pragma unroll
        for (int i = 0; i < 4; i++) { int idx = tid + i * 256; Bs[0][idx >> 6][idx & 63] = rb[i]; }
        __syncthreads();

        int buf = 0;
        for (int kt = 0; kt < ntiles; kt++) {
            const int k0n = (kt + 1) << 4;
            const bool more = (kt + 1) < ntiles;
            if (more) {
#pragma unroll
                for (int i = 0; i < 8; i++) {
                    int idx = tid + i * 256; int m = idx >> 4, k = idx & 15;
                    ra[i] = loadA<AMODE>(A0, A1, A2, bm + m, k0n + k, K, t);
                }
#pragma unroll
                for (int i = 0; i < 4; i++) {
                    int idx = tid + i * 256; int k = idx >> 6, n = idx & 63;
                    rb[i] = (k0n + k < K) ? Bt[(size_t)(k0n + k) * N + bn + n] : 0.0f;
                }
            }
#pragma unroll
            for (int kk = 0; kk < 16; kk += 8) {
                unsigned a[2][4], b[4][2];
#pragma unroll
                for (int tm = 0; tm < 2; tm++) {
                    int row = wm * 32 + tm * 16 + rsel;
                    a[tm][0] = __float_as_uint(As[buf][row][kk + q]);
                    a[tm][1] = __float_as_uint(As[buf][row + 8][kk + q]);
                    a[tm][2] = __float_as_uint(As[buf][row][kk + q + 4]);
                    a[tm][3] = __float_as_uint(As[buf][row + 8][kk + q + 4]);
                }
#pragma unroll
                for (int tn = 0; tn < 4; tn++) {
                    int col = wn * 32 + tn * 8 + rsel;
                    b[tn][0] = __float_as_uint(Bs[buf][kk + q][col]);
                    b[tn][1] = __float_as_uint(Bs[buf][kk + q + 4][col]);
                }
#pragma unroll
                for (int tm = 0; tm < 2; tm++)
#pragma unroll
                    for (int tn = 0; tn < 4; tn++) mma_tf32(acc[tm][tn], a[tm], b[tn]);
            }
            if (more) {
#pragma unroll
                for (int i = 0; i < 8; i++) { int idx = tid + i * 256; As[buf ^ 1][idx >> 4][idx & 15] = ra[i]; }
#pragma unroll
                for (int i = 0; i < 4; i++) { int idx = tid + i * 256; Bs[buf ^ 1][idx >> 6][idx & 63] = rb[i]; }
            }
            __syncthreads();
            buf ^= 1;
        }

        if (EPI == 0) {
#pragma unroll
            for (int tm = 0; tm < 2; tm++)
#pragma unroll
                for (int tn = 0; tn < 4; tn++) {
                    int r0 = bm + wm * 32 + tm * 16 + rsel;
                    int col = bn + wn * 32 + tn * 8 + 2 * q;
                    C[(size_t)r0 * N + col]           = acc[tm][tn][0];
                    C[(size_t)r0 * N + col + 1]       = acc[tm][tn][1];
                    C[(size_t)(r0 + 8) * N + col]     = acc[tm][tn][2];
                    C[(size_t)(r0 + 8) * N + col + 1] = acc[tm][tn][3];
                }
        } else if (EPI == 1) {
#pragma unroll
            for (int tm = 0; tm < 2; tm++)
#pragma unroll
                for (int tn = 0; tn < 4; tn++) {
                    int r0 = bm + wm * 32 + tm * 16 + rsel;
                    int col = bn + wn * 32 + tn * 8 + 2 * q;
                    float b0 = bias[col], b1 = bias[col + 1];
                    C[(size_t)r0 * N + col]           = sigmoidf_(acc[tm][tn][0] + b0);
                    C[(size_t)r0 * N + col + 1]       = sigmoidf_(acc[tm][tn][1] + b1);
                    C[(size_t)(r0 + 8) * N + col]     = sigmoidf_(acc[tm][tn][2] + b0);
                    C[(size_t)(r0 + 8) * N + col + 1] = sigmoidf_(acc[tm][tn][3] + b1);
                }
        } else {
            // permuted gates: col = 4*h + gate, order [i,f,g,o]; even-q lanes (i,f),
            // odd-q partner lane^1 holds (g,o).
#pragma unroll
            for (int tm = 0; tm < 2; tm++)
#pragma unroll
                for (int tn = 0; tn < 4; tn++) {
                    int col = bn + wn * 32 + tn * 8 + 2 * q;
                    float b0 = bias[col], b1 = bias[col + 1];
#pragma unroll
                    for (int half = 0; half < 2; half++) {
                        int r = bm + wm * 32 + tm * 16 + rsel + half * 8;
                        float v0 = acc[tm][tn][half * 2 + 0] + b0;
                        float v1 = acc[tm][tn][half * 2 + 1] + b1;
                        float p0 = __shfl_xor_sync(0xffffffffu, v0, 1);
                        float p1 = __shfl_xor_sync(0xffffffffu, v1, 1);
                        if (!(q & 1)) {
                            int h = col >> 2;
                            float cn = sigmoidf_(v1) * c_in[(size_t)r * H_ + h]
                                     + sigmoidf_(v0) * tanhf(p0);
                            float hn = sigmoidf_(p1) * tanhf(cn);
                            C[(size_t)r * H_ + h] = hn;
                            if (c_out) c_out[(size_t)r * H_ + h] = cn;
                        }
                    }
                }
        }
    }
}

// ---------------- attention phase (enc + dec halves of g_qkv) ----------------
__device__ __forceinline__ void attn_phase() {
    const int w0 = blockIdx.x * 8 + (threadIdx.x >> 5);
    const int lane = threadIdx.x & 31;
    const float scale = 0.17677669529663687f;   // 1/sqrt(32)
    for (int p = w0; p < 2 * R_ * NH_; p += NB * 8) {
        int r = p >> 3;
        int head = p & (NH_ - 1);
        int s = r & (S_ - 1);
        const float* qkv = g_qkv;
        float qv = qkv[(size_t)r * 768 + head * DK_ + lane];
        const int offs[4] = {2, 1, -1, -2};
        float sc[4];
#pragma unroll
        for (int n = 0; n < 4; n++) {
            int sn = s + offs[n];
            float d = 0.0f;
            if (sn >= 0 && sn < S_) {
                int rn = r + offs[n];
                d = qv * qkv[(size_t)rn * 768 + 256 + head * DK_ + lane];
            }
            sc[n] = warp_sum(d) * scale;
        }
        float mx = fmaxf(fmaxf(sc[0], sc[1]), fmaxf(sc[2], sc[3]));
        float e[4], sum = 0.0f;
#pragma unroll
        for (int n = 0; n < 4; n++) { e[n] = __expf(sc[n] - mx); sum += e[n]; }
        float inv = 1.0f / sum;
        float accv = 0.0f;
#pragma unroll
        for (int n = 0; n < 4; n++) {
            int sn = s + offs[n];
            if (sn >= 0 && sn < S_) {
                int rn = r + offs[n];
                accv = fmaf(e[n] * inv, qkv[(size_t)rn * 768 + 512 + head * DK_ + lane], accv);
            }
        }
        float* ctx = (r < R_) ? g_ctx_e : g_ctx_d;
        ctx[(size_t)(r & (R_ - 1)) * H_ + head * DK_ + lane] = accv;
    }
}

// ---------------- output GEMV + assembly (one warp per row) ----------------
__device__ __forceinline__ void out_phase(const float* __restrict__ dh,
                                          const float* __restrict__ W,
                                          const float* __restrict__ bb,
                                          const float* __restrict__ input,
                                          float* __restrict__ dout, int t) {
    const int w = blockIdx.x * 8 + (threadIdx.x >> 5);   // 0..2047 exactly
    const int lane = threadIdx.x & 31;
    int r = w, b = r >> 7, s = r & (S_ - 1);
    float s0 = 0.0f, s1 = 0.0f;
#pragma unroll
    for (int j = 0; j < H_; j += 32) {
        float wv = W[j + lane];
        s0 = fmaf(dh[(size_t)r * H_ + j + lane], wv, s0);
        if (s > 0) s1 = fmaf(dh[(size_t)(r - 1) * H_ + j + lane], wv, s1);
    }
    s0 = warp_sum(s0);
    s1 = warp_sum(s1);
    if (lane == 0) {
        float o  = s0 + bb[0];
        float In = (s > 0) ? (s1 + bb[0])
                           : input[(((size_t)b * T_ + (t + 1)) * S_ + 0) * F_ + 1];
        float num = input[(((size_t)b * T_ + t) * S_ + s) * F_ + 2] + In - o;
        size_t base = (((size_t)b * (T_ - TP_ - 1) + (t - TP_)) * S_ + s) * 3;
        dout[base + 0] = o;
        dout[base + 1] = In;
        dout[base + 2] = num;
    }
}

// ---------------- the persistent kernel ----------------
__global__ __launch_bounds__(256, 2)
void persist_kernel(const float* __restrict__ input,
                    const float* __restrict__ embW, const float* __restrict__ embb,
                    const float* __restrict__ outW, const float* __restrict__ outb,
                    float* __restrict__ dout)
{
    __shared__ float As[2][128][20];
    __shared__ float Bs[2][16][72];

    int ce = 0, cd = 0;
    for (int t = 0; t < T_ - 1; t++) {
        // A: batched enc+dec QKV (M=4096, N=768, K=256)
        gemm_phase<3, 0>(As, Bs, nullptr, g_eh[ce], g_dh[cd], g_We, g_Wd,
                         nullptr, g_qkv, nullptr, nullptr, 32, 12, 768, H_, 0);
        gsync();
        // B: attention (both)
        attn_phase();
        gsync();
        // C: enc gates + LSTM -> eh[ce^1], ec
        gemm_phase<1, 2>(As, Bs, input, g_eh[ce], g_ctx_e, g_Wge, nullptr,
                         g_bge, g_eh[ce ^ 1], g_ec, g_ec, 16, 16, 4 * H_, F_ + 2 * H_, t);
        gsync();
        // D: emb -> code; also output GEMV for step t-1 (underloaded phase)
        gemm_phase<0, 1>(As, Bs, g_eh[ce ^ 1], nullptr, nullptr, embW, nullptr,
                         embb, g_code, nullptr, nullptr, 16, 4, H_, H_, 0);
        if (t - 1 >= TP_) out_phase(g_dh[cd], outW, outb, input, dout, t - 1);
        gsync();
        // E: dec gates + LSTM -> dh[cd^1] (c_in = old dh, c discarded)
        gemm_phase<2, 2>(As, Bs, g_code, g_dh[cd], g_ctx_d, g_Wgd, nullptr,
                         g_bgd, g_dh[cd ^ 1], g_dh[cd], nullptr, 16, 16, 4 * H_, 3 * H_, 0);
        gsync();
        ce ^= 1; cd ^= 1;
    }
    // final output for t = T-2 = 30 (dh already synced by last phase-E gsync)
    out_phase(g_dh[cd], outW, outb, input, dout, T_ - 2);
}

// ---------------- prep kernels ----------------
__global__ void zero_state_kernel() {
    int i = blockIdx.x * blockDim.x + threadIdx.x;
    if (i < R_ * H_) { g_eh[0][i] = 0.0f; g_ec[i] = 0.0f; g_dh[0][i] = 0.0f; }
}

__global__ void concat_w_kernel(const float* __restrict__ Wq, const float* __restrict__ Wk,
                                const float* __restrict__ Wv, float* __restrict__ Wc) {
    int idx = blockIdx.x * blockDim.x + threadIdx.x;
    if (idx >= H_ * 3 * H_) return;
    int k = idx / (3 * H_);
    int n = idx - k * (3 * H_);
    const float* src = (n < H_) ? Wq : ((n < 2 * H_) ? Wk : Wv);
    Wc[idx] = src[k * H_ + (n & (H_ - 1))];
}

__global__ void permute_wg_kernel(const float* __restrict__ W, const float* __restrict__ b,
                                  float* __restrict__ pW, float* __restrict__ pb, int K) {
    int idx = blockIdx.x * blockDim.x + threadIdx.x;
    if (idx >= K * 4 * H_) return;
    int k = idx >> 10;
    int n = idx & (4 * H_ - 1);
    int h = n >> 2, g = n & 3;
    pW[idx] = W[(size_t)k * 4 * H_ + g * H_ + h];
    if (idx < 4 * H_) pb[idx] = b[g * H_ + h];
}

// ---------------- host side ----------------
extern "C" void kernel_launch(void* const* d_in, const int* in_sizes, int n_in,
                              void* d_out, int out_size) {
    const float* input = (const float*)d_in[0];
    const float* eWq = (const float*)d_in[1];
    const float* eWk = (const float*)d_in[2];
    const float* eWv = (const float*)d_in[3];
    const float* eWg = (const float*)d_in[4];
    const float* ebg = (const float*)d_in[5];
    const float* dWq = (const float*)d_in[6];
    const float* dWk = (const float*)d_in[7];
    const float* dWv = (const float*)d_in[8];
    const float* dWg = (const float*)d_in[9];
    const float* dbg = (const float*)d_in[10];
    const float* embW = (const float*)d_in[11];
    const float* embb = (const float*)d_in[12];
    const float* outW = (const float*)d_in[13];
    const float* outb = (const float*)d_in[14];
    float* dout = (float*)d_out;

    float *p_We, *p_Wd, *p_Wge, *p_Wgd, *p_bge, *p_bgd;
    cudaGetSymbolAddress((void**)&p_We,  g_We);
    cudaGetSymbolAddress((void**)&p_Wd,  g_Wd);
    cudaGetSymbolAddress((void**)&p_Wge, g_Wge);
    cudaGetSymbolAddress((void**)&p_Wgd, g_Wgd);
    cudaGetSymbolAddress((void**)&p_bge, g_bge);
    cudaGetSymbolAddress((void**)&p_bgd, g_bgd);

    const int KE = F_ + 2 * H_;
    const int KD = 3 * H_;

    zero_state_kernel<<<(R_ * H_ + 255) / 256, 256>>>();
    concat_w_kernel<<<(H_ * 3 * H_ + 255) / 256, 256>>>(eWq, eWk, eWv, p_We);
    concat_w_kernel<<<(H_ * 3 * H_ + 255) / 256, 256>>>(dWq, dWk, dWv, p_Wd);
    permute_wg_kernel<<<(KE * 4 * H_ + 255) / 256, 256>>>(eWg, ebg, p_Wge, p_bge, KE);
    permute_wg_kernel<<<(KD * 4 * H_ + 255) / 256, 256>>>(dWg, dbg, p_Wgd, p_bgd, KD);

    persist_kernel<<<NB, 256>>>(input, embW, embb, outW, outb, dout);
}